// round 10
// baseline (speedup 1.0000x reference)
#include <cuda_runtime.h>
#include <cstdint>

#define SQ_ 0.09016844005556022f   // (1/16)*log2(e)

static __device__ float g_Q [18874368];   // [g][s][d]  scaled by SQ_, tf32-rounded
static __device__ float g_K [18874368];   // [g][s][d]  tf32-rounded
static __device__ float g_Vt[18874368];   // [g][e][s]  tf32-rounded

__device__ __forceinline__ uint32_t smem_u32(const void* p) {
    uint32_t a;
    asm("{ .reg .u64 t; cvta.to.shared.u64 t, %1; cvt.u32.u64 %0, t; }" : "=r"(a) : "l"(p));
    return a;
}
__device__ __forceinline__ void cpa16(uint32_t d, const void* s) {
    asm volatile("cp.async.cg.shared.global [%0], [%1], 16;\n" :: "r"(d), "l"(s));
}
#define CP_COMMIT  asm volatile("cp.async.commit_group;\n" ::: "memory")
#define CP_WAIT(n) asm volatile("cp.async.wait_group %0;\n" :: "n"(n) : "memory")

__device__ __forceinline__ uint32_t f2tf(float x) {
    uint32_t u; asm("cvt.rna.tf32.f32 %0, %1;" : "=r"(u) : "f"(x)); return u;
}
__device__ __forceinline__ void mma8(float* c, const uint32_t* a, const uint32_t* b) {
    asm volatile("mma.sync.aligned.m16n8k8.row.col.f32.tf32.tf32.f32 "
                 "{%0,%1,%2,%3}, {%4,%5,%6,%7}, {%8,%9}, {%0,%1,%2,%3};\n"
                 : "+f"(c[0]), "+f"(c[1]), "+f"(c[2]), "+f"(c[3])
                 : "r"(a[0]), "r"(a[1]), "r"(a[2]), "r"(a[3]), "r"(b[0]), "r"(b[1]));
}
__device__ __forceinline__ void mbar_init(uint32_t a, uint32_t c) {
    asm volatile("mbarrier.init.shared.b64 [%0], %1;" :: "r"(a), "r"(c) : "memory");
}
__device__ __forceinline__ void mbar_arrive(uint32_t a) {
    asm volatile("mbarrier.arrive.shared.b64 _, [%0];" :: "r"(a) : "memory");
}
__device__ __forceinline__ void mbar_cp_arrive(uint32_t a) {
    asm volatile("cp.async.mbarrier.arrive.noinc.shared.b64 [%0];" :: "r"(a) : "memory");
}
__device__ __forceinline__ void mbar_wait(uint32_t a, uint32_t ph) {
    asm volatile("{\n\t.reg .pred P;\n\tWL_%=:\n\t"
                 "mbarrier.try_wait.parity.acquire.cta.shared::cta.b64 P, [%0], %1, 0x989680;\n\t"
                 "@P bra.uni WD_%=;\n\tbra.uni WL_%=;\n\tWD_%=:\n\t}"
                 :: "r"(a), "r"(ph) : "memory");
}

// ============================================================
// QKV (unchanged): CTA 128x128, K-chunks 32, 256 thr, 3-stage ring.
// ============================================================
#define QKV_SMEM 110592

__global__ void __launch_bounds__(256, 2)
qkv_mma(const float* __restrict__ x,
        const float* __restrict__ Wq, const float* __restrict__ bq,
        const float* __restrict__ Wk, const float* __restrict__ bk,
        const float* __restrict__ Wv, const float* __restrict__ bv)
{
    extern __shared__ float smf[];
    float* As = smf;            // 3 x 4608
    float* Bs = smf + 13824;    // 3 x 4608

    const int tile = blockIdx.x, g = blockIdx.y, z = blockIdx.z;
    const int tm = tile >> 1, tn = tile & 1;
    const int hh = g % 3;
    const int tid = threadIdx.x, wid = tid >> 5, lane = tid & 31;
    const int ty = lane >> 2, tx = lane & 3;
    const int warpM = wid >> 1, warpN = wid & 1;
    const int rb = warpM * 32, nb = warpN * 64;

    const float* W; const float* bias;
    if (z == 0)      { W = Wq; bias = bq; }
    else if (z == 1) { W = Wk; bias = bk; }
    else             { W = Wv; bias = bv; }
    W += hh * 65536;  bias += hh * 256;

    const float* X  = x + ((size_t)((g / 3) * 1024 + tm * 128)) * 768 + hh * 256;
    const float* Wp = W + tn * 128 * 256;
    const uint32_t sA = smem_u32(As), sB = smem_u32(Bs);

    auto stage = [&](int dc_) {
        if (dc_ >= 8) return;
        const int bf_ = dc_ % 3;
        uint32_t dA = sA + bf_ * 18432, dB = sB + bf_ * 18432;
#pragma unroll
        for (int it = 0; it < 4; it++) {
            int i = tid + it * 256, r = i >> 3, c4 = i & 7;
            cpa16(dA + r * 144 + c4 * 16, X  + (size_t)r * 768 + dc_ * 32 + c4 * 4);
            cpa16(dB + r * 144 + c4 * 16, Wp + r * 256 + dc_ * 32 + c4 * 4);
        }
        CP_COMMIT;
    };

    float acc[2][8][4];
#pragma unroll
    for (int mf = 0; mf < 2; mf++)
#pragma unroll
        for (int nf = 0; nf < 8; nf++)
#pragma unroll
            for (int k = 0; k < 4; k++) acc[mf][nf][k] = 0.f;

    stage(0); stage(1);
#pragma unroll 1
    for (int dc = 0; dc < 8; dc++) {
        const int bf = dc % 3;
        CP_WAIT(1);
        __syncthreads();
        stage(dc + 2);
        const float* Aq = As + bf * 4608;
        const float* Bk = Bs + bf * 4608;
#pragma unroll
        for (int ks = 0; ks < 4; ks++) {
            uint32_t af[2][4], bfr[8][2];
            const int kc = ks * 8 + tx;
#pragma unroll
            for (int mf = 0; mf < 2; mf++) {
                const float* ap = Aq + (rb + mf * 16 + ty) * 36 + kc;
                af[mf][0] = f2tf(ap[0]);
                af[mf][1] = f2tf(ap[8 * 36]);
                af[mf][2] = f2tf(ap[4]);
                af[mf][3] = f2tf(ap[8 * 36 + 4]);
            }
#pragma unroll
            for (int nf = 0; nf < 8; nf++) {
                const float* bp = Bk + (nb + nf * 8 + ty) * 36 + kc;
                bfr[nf][0] = f2tf(bp[0]);
                bfr[nf][1] = f2tf(bp[4]);
            }
#pragma unroll
            for (int mf = 0; mf < 2; mf++)
#pragma unroll
                for (int nf = 0; nf < 8; nf++)
                    mma8(acc[mf][nf], af[mf], bfr[nf]);
        }
    }

    if (z < 2) {
        float* dst = (z == 0 ? g_Q : g_K) + (size_t)g * 262144;
        const float osc = (z == 0) ? SQ_ : 1.0f;
#pragma unroll
        for (int mf = 0; mf < 2; mf++) {
            const int r0 = tm * 128 + rb + mf * 16 + ty, r1 = r0 + 8;
#pragma unroll
            for (int nf = 0; nf < 8; nf++) {
                const int ccol = tn * 128 + nb + nf * 8 + tx * 2;
                const float b0 = __ldg(&bias[ccol]), b1 = __ldg(&bias[ccol + 1]);
                *(float2*)&dst[(size_t)r0 * 256 + ccol] = make_float2(
                    __uint_as_float(f2tf((acc[mf][nf][0] + b0) * osc)),
                    __uint_as_float(f2tf((acc[mf][nf][1] + b1) * osc)));
                *(float2*)&dst[(size_t)r1 * 256 + ccol] = make_float2(
                    __uint_as_float(f2tf((acc[mf][nf][2] + b0) * osc)),
                    __uint_as_float(f2tf((acc[mf][nf][3] + b1) * osc)));
            }
        }
    } else {
        float* dst = g_Vt + (size_t)g * 262144;
#pragma unroll
        for (int mf = 0; mf < 2; mf++) {
            const int r0 = tm * 128 + rb + mf * 16 + ty, r1 = r0 + 8;
#pragma unroll
            for (int nf = 0; nf < 8; nf++) {
                const int e0 = tn * 128 + nb + nf * 8 + tx * 2;
                const float b0 = __ldg(&bias[e0]), b1 = __ldg(&bias[e0 + 1]);
                dst[(size_t)e0 * 1024 + r0]       = __uint_as_float(f2tf(acc[mf][nf][0] + b0));
                dst[(size_t)(e0 + 1) * 1024 + r0] = __uint_as_float(f2tf(acc[mf][nf][1] + b1));
                dst[(size_t)e0 * 1024 + r1]       = __uint_as_float(f2tf(acc[mf][nf][2] + b0));
                dst[(size_t)(e0 + 1) * 1024 + r1] = __uint_as_float(f2tf(acc[mf][nf][3] + b1));
            }
        }
    }
}

// ============================================================
// Attention: per (qtile=128, g).  256 thr, 8 warps (4M x 2N).
// Producer/consumer mbarrier ring, depth 4.  Chunk idx in [0,128):
//   per t (idx>>4): c=idx&15; c<8 -> QK d-chunk c; else Vt 16-key chunk c-8.
// Chunk idx staged entirely by warp (idx%8); full[slot] count=32 (cp-arrives),
// empty[slot] count=8.  TWO __syncthreads per t: after softmax (P write->read)
// and after PV loop (P read -> next-t P write).
// smem: A 4x4608f | B 4x5120f | P 128x132 | lp 256f | mbar 64B = 224320 B
// ============================================================
#define ATT_SMEM 224320

__global__ void __launch_bounds__(256, 1)
attn_mma(float* __restrict__ out)
{
    extern __shared__ float smf[];
    float* As = smf;                 // 4 x 4608
    float* Bs = smf + 18432;         // 4 x 5120
    float* Ps = smf + 38912;         // 128 x 132 (tf32-rounded)
    float* lp = smf + 55808;         // 256

    const int qt = blockIdx.x, g = blockIdx.y;
    const int bb = g / 9, cc = (g / 3) % 3, hh = g % 3;
    const int q0 = qt * 128;
    const int tid = threadIdx.x, wid = tid >> 5, lane = tid & 31;
    const int ty = lane >> 2, tx = lane & 3;
    const int warpM = wid >> 1, warpN = wid & 1;
    const int rb = warpM * 32, nbS = warpN * 64, nbO = warpN * 128;
    const size_t gbase = (size_t)g * 262144;
    const float* Qg = g_Q + gbase + (size_t)q0 * 256;
    const float* Kg = g_K + gbase;
    const float* Vg = g_Vt + gbase;
    const uint32_t sA = smem_u32(As), sB = sA + 73728;
    const uint32_t mbB = sA + 224256;          // 4 full @ +0, 4 empty @ +32
    const uint32_t* Pu = (const uint32_t*)Ps;

    if (tid == 0) {
#pragma unroll
        for (int s = 0; s < 4; s++) {
            mbar_init(mbB + s * 8, 32);        // full: 32 cp-arrives
            mbar_init(mbB + 32 + s * 8, 8);    // empty: 8 warp-arrives
        }
    }
    __syncthreads();

    // stage chunk j (whole chunk by one warp, 32 lanes)
    auto stage = [&](int j) {
        const int tt = j >> 4, c = j & 15, slot = j & 3;
        if (j >= 4) mbar_wait(mbB + 32 + slot * 8, (uint32_t)(((j >> 2) - 1) & 1));
        if (c < 8) {
            const float* Qc = Qg + c * 32;
            const float* Kc = Kg + (size_t)tt * 32768 + c * 32;
            uint32_t dA = sA + slot * 18432, dB = sB + slot * 20480;
#pragma unroll
            for (int it = 0; it < 32; it++) {
                int i = lane + it * 32, r = i >> 3, c4 = i & 7;
                cpa16(dA + r * 144 + c4 * 16, Qc + (size_t)r * 256 + c4 * 4);
            }
#pragma unroll
            for (int it = 0; it < 32; it++) {
                int i = lane + it * 32, r = i >> 3, c4 = i & 7;
                cpa16(dB + r * 144 + c4 * 16, Kc + (size_t)r * 256 + c4 * 4);
            }
        } else {
            const float* Vc = Vg + tt * 128 + (c - 8) * 16;
            uint32_t dB = sB + slot * 20480;
#pragma unroll
            for (int it = 0; it < 32; it++) {   // 256 e-rows x 4 float4 = 1024
                int i = lane + it * 32, e = i >> 2, c4 = i & 3;
                cpa16(dB + e * 80 + c4 * 16, Vc + (size_t)e * 1024 + c4 * 4);
            }
        }
        mbar_cp_arrive(mbB + slot * 8);
    };

    float Oac[2][16][4];
    float Sac[2][8][4];
    float lac[4] = {0.f, 0.f, 0.f, 0.f};
#pragma unroll
    for (int mf = 0; mf < 2; mf++)
#pragma unroll
        for (int nf = 0; nf < 16; nf++)
#pragma unroll
            for (int k = 0; k < 4; k++) Oac[mf][nf][k] = 0.f;

    // prime ring: chunks 0..2 (lookahead 3)
    if (wid == 0) stage(0);
    if (wid == 1) stage(1);
    if (wid == 2) stage(2);

#pragma unroll 1
    for (int t = 0; t < 8; t++) {
#pragma unroll
        for (int mf = 0; mf < 2; mf++)
#pragma unroll
            for (int nf = 0; nf < 8; nf++)
#pragma unroll
                for (int k = 0; k < 4; k++) Sac[mf][nf][k] = 0.f;

        // ---- S = Q·K^T : 8 QK chunks ----
#pragma unroll 1
        for (int dc = 0; dc < 8; dc++) {
            const int idx = t * 16 + dc, j = idx + 3, slot = idx & 3;
            if (j < 128 && (j & 7) == wid) stage(j);
            mbar_wait(mbB + slot * 8, (uint32_t)((idx >> 2) & 1));
            const uint32_t* Aq = (const uint32_t*)(As + slot * 4608);
            const uint32_t* Bk = (const uint32_t*)(Bs + slot * 5120);
#pragma unroll
            for (int ks = 0; ks < 4; ks++) {
                uint32_t af[2][4], bfr[8][2];
                const int kc = ks * 8 + tx;
#pragma unroll
                for (int mf = 0; mf < 2; mf++) {
                    const uint32_t* ap = Aq + (rb + mf * 16 + ty) * 36 + kc;
                    af[mf][0] = ap[0];
                    af[mf][1] = ap[8 * 36];
                    af[mf][2] = ap[4];
                    af[mf][3] = ap[8 * 36 + 4];
                }
#pragma unroll
                for (int nf = 0; nf < 8; nf++) {
                    const uint32_t* bp = Bk + (nbS + nf * 8 + ty) * 36 + kc;
                    bfr[nf][0] = bp[0];
                    bfr[nf][1] = bp[4];
                }
#pragma unroll
                for (int mf = 0; mf < 2; mf++)
#pragma unroll
                    for (int nf = 0; nf < 8; nf++)
                        mma8(Sac[mf][nf], af[mf], bfr[nf]);
            }
            __syncwarp();
            if (lane == 0) mbar_arrive(mbB + 32 + slot * 8);
        }

        // ---- softmax: P = exp2(S) (ref max 0), running row sums ----
#pragma unroll
        for (int mf = 0; mf < 2; mf++) {
            const int r = rb + mf * 16 + ty;
#pragma unroll
            for (int nf = 0; nf < 8; nf++) {
                float e0 = exp2f(Sac[mf][nf][0]);
                float e1 = exp2f(Sac[mf][nf][1]);
                float e2 = exp2f(Sac[mf][nf][2]);
                float e3 = exp2f(Sac[mf][nf][3]);
                lac[mf * 2]     += e0 + e1;
                lac[mf * 2 + 1] += e2 + e3;
                const int ccol = nbS + nf * 8 + tx * 2;
                *(float2*)&Ps[r * 132 + ccol] = make_float2(
                    __uint_as_float(f2tf(e0)), __uint_as_float(f2tf(e1)));
                *(float2*)&Ps[(r + 8) * 132 + ccol] = make_float2(
                    __uint_as_float(f2tf(e2)), __uint_as_float(f2tf(e3)));
            }
        }
        __syncthreads();   // all P writes visible before any PV read

        // ---- O += P·Vt : 8 Vt chunks ----
#pragma unroll 1
        for (int jc = 0; jc < 8; jc++) {
            const int idx = t * 16 + 8 + jc, j = idx + 3, slot = idx & 3;
            if (j < 128 && (j & 7) == wid) stage(j);
            mbar_wait(mbB + slot * 8, (uint32_t)((idx >> 2) & 1));
            const uint32_t* Vt_ = (const uint32_t*)(Bs + slot * 5120);
#pragma unroll
            for (int ks = 0; ks < 2; ks++) {
                uint32_t af[2][4], bfr[16][2];
                const int pc = jc * 16 + ks * 8 + tx;
#pragma unroll
                for (int mf = 0; mf < 2; mf++) {
                    const uint32_t* pp = Pu + (rb + mf * 16 + ty) * 132 + pc;
                    af[mf][0] = pp[0];
                    af[mf][1] = pp[8 * 132];
                    af[mf][2] = pp[4];
                    af[mf][3] = pp[8 * 132 + 4];
                }
#pragma unroll
                for (int nf = 0; nf < 16; nf++) {
                    const uint32_t* vp = Vt_ + (nbO + nf * 8 + ty) * 20 + ks * 8 + tx;
                    bfr[nf][0] = vp[0];
                    bfr[nf][1] = vp[4];
                }
#pragma unroll
                for (int mf = 0; mf < 2; mf++)
#pragma unroll
                    for (int nf = 0; nf < 16; nf++)
                        mma8(Oac[mf][nf], af[mf], bfr[nf]);
            }
            __syncwarp();
            if (lane == 0) mbar_arrive(mbB + 32 + slot * 8);
        }
        __syncthreads();   // all P reads done before next t overwrites P
    }

    // ---- epilogue: reduce row sums, O/l, store ----
#pragma unroll
    for (int i = 0; i < 4; i++) {
        lac[i] += __shfl_xor_sync(0xffffffffu, lac[i], 1);
        lac[i] += __shfl_xor_sync(0xffffffffu, lac[i], 2);
    }
    if (tx == 0) {
#pragma unroll
        for (int mf = 0; mf < 2; mf++) {
            lp[warpN * 128 + rb + mf * 16 + ty]     = lac[mf * 2];
            lp[warpN * 128 + rb + mf * 16 + ty + 8] = lac[mf * 2 + 1];
        }
    }
    __syncthreads();
#pragma unroll
    for (int mf = 0; mf < 2; mf++) {
        const int r0 = rb + mf * 16 + ty, r1 = r0 + 8;
        const float inv0 = 1.f / (lp[r0] + lp[128 + r0]);
        const float inv1 = 1.f / (lp[r1] + lp[128 + r1]);
        float* o0 = out + ((size_t)(bb * 1024 + q0 + r0)) * 2304 + cc * 768 + hh * 256 + nbO;
        float* o1 = out + ((size_t)(bb * 1024 + q0 + r1)) * 2304 + cc * 768 + hh * 256 + nbO;
#pragma unroll
        for (int nf = 0; nf < 16; nf++) {
            const int ccol = nf * 8 + tx * 2;
            *(float2*)&o0[ccol] = make_float2(Oac[mf][nf][0] * inv0, Oac[mf][nf][1] * inv0);
            *(float2*)&o1[ccol] = make_float2(Oac[mf][nf][2] * inv1, Oac[mf][nf][3] * inv1);
        }
    }
}

// ============================================================
extern "C" void kernel_launch(void* const* d_in, const int* in_sizes, int n_in,
                              void* d_out, int out_size)
{
    const float* x  = (const float*)d_in[0];
    const float* Wq = (const float*)d_in[1];
    const float* bq = (const float*)d_in[2];
    const float* Wk = (const float*)d_in[3];
    const float* bk = (const float*)d_in[4];
    const float* Wv = (const float*)d_in[5];
    const float* bv = (const float*)d_in[6];
    float* out = (float*)d_out;

    cudaFuncSetAttribute(qkv_mma,  cudaFuncAttributeMaxDynamicSharedMemorySize, QKV_SMEM);
    cudaFuncSetAttribute(attn_mma, cudaFuncAttributeMaxDynamicSharedMemorySize, ATT_SMEM);

    qkv_mma<<<dim3(16, 72, 3), 256, QKV_SMEM>>>(x, Wq, bq, Wk, bk, Wv, bv);
    attn_mma<<<dim3(8, 72), 256, ATT_SMEM>>>(out);
}

// round 11
// speedup vs baseline: 1.0439x; 1.0439x over previous
#include <cuda_runtime.h>
#include <cstdint>

#define SQ_ 0.09016844005556022f   // (1/16)*log2(e)

static __device__ float g_Q [18874368];   // [g][s][d]  scaled by SQ_, tf32-rounded
static __device__ float g_K [18874368];   // [g][s][d]  tf32-rounded
static __device__ float g_Vt[18874368];   // [g][e][s]  tf32-rounded

__device__ __forceinline__ uint32_t smem_u32(const void* p) {
    uint32_t a;
    asm("{ .reg .u64 t; cvta.to.shared.u64 t, %1; cvt.u32.u64 %0, t; }" : "=r"(a) : "l"(p));
    return a;
}
__device__ __forceinline__ void cpa16(uint32_t d, const void* s) {
    asm volatile("cp.async.cg.shared.global [%0], [%1], 16;\n" :: "r"(d), "l"(s));
}
#define CP_COMMIT  asm volatile("cp.async.commit_group;\n" ::: "memory")
#define CP_WAIT(n) asm volatile("cp.async.wait_group %0;\n" :: "n"(n) : "memory")

__device__ __forceinline__ uint32_t f2tf(float x) {
    uint32_t u; asm("cvt.rna.tf32.f32 %0, %1;" : "=r"(u) : "f"(x)); return u;
}
__device__ __forceinline__ float ex2f(float x) {
    float y; asm("ex2.approx.ftz.f32 %0, %1;" : "=f"(y) : "f"(x)); return y;
}
__device__ __forceinline__ void mma8(float* c, const uint32_t* a, const uint32_t b0, const uint32_t b1) {
    asm volatile("mma.sync.aligned.m16n8k8.row.col.f32.tf32.tf32.f32 "
                 "{%0,%1,%2,%3}, {%4,%5,%6,%7}, {%8,%9}, {%0,%1,%2,%3};\n"
                 : "+f"(c[0]), "+f"(c[1]), "+f"(c[2]), "+f"(c[3])
                 : "r"(a[0]), "r"(a[1]), "r"(a[2]), "r"(a[3]), "r"(b0), "r"(b1));
}
// x4 ldmatrix: 4 8x8-b16 matrices; lanes 0-7/8-15/16-23/24-31 give matrix row addrs.
__device__ __forceinline__ void ldsm4(uint32_t* r, uint32_t addr) {
    asm volatile("ldmatrix.sync.aligned.m8n8.x4.shared.b16 {%0,%1,%2,%3}, [%4];"
                 : "=r"(r[0]), "=r"(r[1]), "=r"(r[2]), "=r"(r[3]) : "r"(addr));
}

// ============================================================
// QKV (identical to r7 — the proven 759us version): CTA 128x128, 256 thr,
// 3-stage cp.async ring.  Outputs tf32-rounded; Q pre-scaled; V transposed.
// ============================================================
#define QKV_SMEM 110592

__global__ void __launch_bounds__(256, 2)
qkv_mma(const float* __restrict__ x,
        const float* __restrict__ Wq, const float* __restrict__ bq,
        const float* __restrict__ Wk, const float* __restrict__ bk,
        const float* __restrict__ Wv, const float* __restrict__ bv)
{
    extern __shared__ float smf[];
    float* As = smf;            // 3 x 4608
    float* Bs = smf + 13824;    // 3 x 4608

    const int tile = blockIdx.x, g = blockIdx.y, z = blockIdx.z;
    const int tm = tile >> 1, tn = tile & 1;
    const int hh = g % 3;
    const int tid = threadIdx.x, wid = tid >> 5, lane = tid & 31;
    const int ty = lane >> 2, tx = lane & 3;
    const int warpM = wid >> 1, warpN = wid & 1;
    const int rb = warpM * 32, nb = warpN * 64;

    const float* W; const float* bias;
    if (z == 0)      { W = Wq; bias = bq; }
    else if (z == 1) { W = Wk; bias = bk; }
    else             { W = Wv; bias = bv; }
    W += hh * 65536;  bias += hh * 256;

    const float* X  = x + ((size_t)((g / 3) * 1024 + tm * 128)) * 768 + hh * 256;
    const float* Wp = W + tn * 128 * 256;
    const uint32_t sA = smem_u32(As), sB = smem_u32(Bs);

    auto stage = [&](int dc_) {
        if (dc_ >= 8) return;
        const int bf_ = dc_ % 3;
        uint32_t dA = sA + bf_ * 18432, dB = sB + bf_ * 18432;
#pragma unroll
        for (int it = 0; it < 4; it++) {
            int i = tid + it * 256, r = i >> 3, c4 = i & 7;
            cpa16(dA + r * 144 + c4 * 16, X  + (size_t)r * 768 + dc_ * 32 + c4 * 4);
            cpa16(dB + r * 144 + c4 * 16, Wp + r * 256 + dc_ * 32 + c4 * 4);
        }
        CP_COMMIT;
    };

    float acc[2][8][4];
#pragma unroll
    for (int mf = 0; mf < 2; mf++)
#pragma unroll
        for (int nf = 0; nf < 8; nf++)
#pragma unroll
            for (int k = 0; k < 4; k++) acc[mf][nf][k] = 0.f;

    stage(0); stage(1);
#pragma unroll 1
    for (int dc = 0; dc < 8; dc++) {
        const int bf = dc % 3;
        CP_WAIT(1);
        __syncthreads();
        stage(dc + 2);
        const float* Aq = As + bf * 4608;
        const float* Bk = Bs + bf * 4608;
#pragma unroll
        for (int ks = 0; ks < 4; ks++) {
            uint32_t af[2][4], bfr[8][2];
            const int kc = ks * 8 + tx;
#pragma unroll
            for (int mf = 0; mf < 2; mf++) {
                const float* ap = Aq + (rb + mf * 16 + ty) * 36 + kc;
                af[mf][0] = f2tf(ap[0]);
                af[mf][1] = f2tf(ap[8 * 36]);
                af[mf][2] = f2tf(ap[4]);
                af[mf][3] = f2tf(ap[8 * 36 + 4]);
            }
#pragma unroll
            for (int nf = 0; nf < 8; nf++) {
                const float* bp = Bk + (nb + nf * 8 + ty) * 36 + kc;
                bfr[nf][0] = f2tf(bp[0]);
                bfr[nf][1] = f2tf(bp[4]);
            }
#pragma unroll
            for (int mf = 0; mf < 2; mf++)
#pragma unroll
                for (int nf = 0; nf < 8; nf++)
                    mma8(acc[mf][nf], af[mf], bfr[nf][0], bfr[nf][1]);
        }
    }

    if (z < 2) {
        float* dst = (z == 0 ? g_Q : g_K) + (size_t)g * 262144;
        const float osc = (z == 0) ? SQ_ : 1.0f;
#pragma unroll
        for (int mf = 0; mf < 2; mf++) {
            const int r0 = tm * 128 + rb + mf * 16 + ty, r1 = r0 + 8;
#pragma unroll
            for (int nf = 0; nf < 8; nf++) {
                const int ccol = tn * 128 + nb + nf * 8 + tx * 2;
                const float b0 = __ldg(&bias[ccol]), b1 = __ldg(&bias[ccol + 1]);
                *(float2*)&dst[(size_t)r0 * 256 + ccol] = make_float2(
                    __uint_as_float(f2tf((acc[mf][nf][0] + b0) * osc)),
                    __uint_as_float(f2tf((acc[mf][nf][1] + b1) * osc)));
                *(float2*)&dst[(size_t)r1 * 256 + ccol] = make_float2(
                    __uint_as_float(f2tf((acc[mf][nf][2] + b0) * osc)),
                    __uint_as_float(f2tf((acc[mf][nf][3] + b1) * osc)));
            }
        }
    } else {
        float* dst = g_Vt + (size_t)g * 262144;
#pragma unroll
        for (int mf = 0; mf < 2; mf++) {
            const int r0 = tm * 128 + rb + mf * 16 + ty, r1 = r0 + 8;
#pragma unroll
            for (int nf = 0; nf < 8; nf++) {
                const int e0 = tn * 128 + nb + nf * 8 + tx * 2;
                const float b0 = __ldg(&bias[e0]), b1 = __ldg(&bias[e0 + 1]);
                dst[(size_t)e0 * 1024 + r0]       = __uint_as_float(f2tf(acc[mf][nf][0] + b0));
                dst[(size_t)(e0 + 1) * 1024 + r0] = __uint_as_float(f2tf(acc[mf][nf][1] + b1));
                dst[(size_t)e0 * 1024 + r1]       = __uint_as_float(f2tf(acc[mf][nf][2] + b0));
                dst[(size_t)(e0 + 1) * 1024 + r1] = __uint_as_float(f2tf(acc[mf][nf][3] + b1));
            }
        }
    }
}

// ============================================================
// Attention (r7 control flow + ldmatrix fragment loads).
// per (qtile=128, g), 256 thr, 8 warps (4M x 2N).
// S warp-tile 32x64; PV warp-tile 32x128. 3-stage global cp.async ring over
// 128 chunks (per t: 8 QK then 8 Vt).  All fragment loads via ldmatrix.x4.
// smem: A 3x4608 | B 3x5120 | P 128x132 | lp 256  = 185344 B
// ============================================================
#define ATT_SMEM 185344

__global__ void __launch_bounds__(256, 1)
attn_mma(float* __restrict__ out)
{
    extern __shared__ float smf[];
    float* As = smf;                 // 3 x 4608
    float* Bs = smf + 13824;         // 3 x 5120
    float* Ps = smf + 29184;         // 128 x 132 (tf32-rounded)
    float* lp = smf + 46080;         // 256

    const int qt = blockIdx.x, g = blockIdx.y;
    const int bb = g / 9, cc = (g / 3) % 3, hh = g % 3;
    const int q0 = qt * 128;
    const int tid = threadIdx.x, wid = tid >> 5, lane = tid & 31;
    const int ty = lane >> 2, tx = lane & 3;
    const int warpM = wid >> 1, warpN = wid & 1;
    const int rb = warpM * 32, nbS = warpN * 64, nbO = warpN * 128;
    const size_t gbase = (size_t)g * 262144;
    const float* Qg = g_Q + gbase + (size_t)q0 * 256;
    const float* Kg = g_K + gbase;
    const float* Vg = g_Vt + gbase;
    const uint32_t sA = smem_u32(As), sB = smem_u32(Bs), sP = smem_u32(Ps);

    // ldmatrix per-lane row addressing: row = lane&15 within 16-row tile,
    // k-half = (lane>>4)*16 bytes.
    const int lrow = lane & 15;
    const int lkh  = (lane >> 4) * 16;
    const uint32_t aOffS = (uint32_t)((rb + lrow) * 144 + lkh);        // Q rows, 36f pad
    const uint32_t bOffS = (uint32_t)((nbS + lrow) * 144 + lkh);       // K rows
    const uint32_t pOff  = sP + (uint32_t)((rb + lrow) * 528 + lkh);   // P rows, 132f pad
    const uint32_t vOff  = (uint32_t)((nbO + lrow) * 80 + lkh);        // Vt rows, 20f pad

    auto stage = [&](int idx) {
        if (idx >= 128) return;
        const int t_ = idx >> 4, c_ = idx & 15, bf_ = idx % 3;
        if (c_ < 8) {
            const float* Qc = Qg + c_ * 32;
            const float* Kc = Kg + (size_t)t_ * 32768 + c_ * 32;
            uint32_t dA = sA + bf_ * 18432, dB = sB + bf_ * 20480;
#pragma unroll
            for (int it = 0; it < 4; it++) {
                int i = tid + it * 256, r = i >> 3, c4 = i & 7;
                cpa16(dA + r * 144 + c4 * 16, Qc + (size_t)r * 256 + c4 * 4);
                cpa16(dB + r * 144 + c4 * 16, Kc + (size_t)r * 256 + c4 * 4);
            }
        } else {
            const float* Vc = Vg + t_ * 128 + (c_ - 8) * 16;
            uint32_t dB = sB + bf_ * 20480;
#pragma unroll
            for (int it = 0; it < 4; it++) {
                int i = tid + it * 256, e = i >> 2, c4 = i & 3;
                cpa16(dB + e * 80 + c4 * 16, Vc + (size_t)e * 1024 + c4 * 4);
            }
        }
        CP_COMMIT;
    };

    float Oac[2][16][4];
    float Sac[2][8][4];
    float lac[4] = {0.f, 0.f, 0.f, 0.f};
#pragma unroll
    for (int mf = 0; mf < 2; mf++)
#pragma unroll
        for (int nf = 0; nf < 16; nf++)
#pragma unroll
            for (int k = 0; k < 4; k++) Oac[mf][nf][k] = 0.f;

    stage(0); stage(1);

#pragma unroll 1
    for (int t = 0; t < 8; t++) {
#pragma unroll
        for (int mf = 0; mf < 2; mf++)
#pragma unroll
            for (int nf = 0; nf < 8; nf++)
#pragma unroll
                for (int k = 0; k < 4; k++) Sac[mf][nf][k] = 0.f;

        // ---- S = Q·K^T : 8 QK chunks ----
#pragma unroll 1
        for (int dc = 0; dc < 8; dc++) {
            const int idx = t * 16 + dc;
            const int bf = idx % 3;
            CP_WAIT(1);
            __syncthreads();
            stage(idx + 2);
            const uint32_t aB = sA + bf * 18432 + aOffS;
            const uint32_t bB = sB + bf * 20480 + bOffS;
#pragma unroll
            for (int ks = 0; ks < 4; ks++) {
                uint32_t af[2][4], bf4[4][4];
                ldsm4(af[0], aB + ks * 32);
                ldsm4(af[1], aB + 16 * 144 + ks * 32);
#pragma unroll
                for (int p = 0; p < 4; p++)
                    ldsm4(bf4[p], bB + p * 16 * 144 + ks * 32);
                // bf4[p] = { b0(nf=2p), b0(nf=2p+1), b1(nf=2p), b1(nf=2p+1) }
#pragma unroll
                for (int mf = 0; mf < 2; mf++)
#pragma unroll
                    for (int p = 0; p < 4; p++) {
                        mma8(Sac[mf][2 * p],     af[mf], bf4[p][0], bf4[p][2]);
                        mma8(Sac[mf][2 * p + 1], af[mf], bf4[p][1], bf4[p][3]);
                    }
            }
        }

        // ---- softmax: P = exp2(S) (ref max 0), running row sums ----
#pragma unroll
        for (int mf = 0; mf < 2; mf++) {
            const int r = rb + mf * 16 + ty;
#pragma unroll
            for (int nf = 0; nf < 8; nf++) {
                float e0 = ex2f(Sac[mf][nf][0]);
                float e1 = ex2f(Sac[mf][nf][1]);
                float e2 = ex2f(Sac[mf][nf][2]);
                float e3 = ex2f(Sac[mf][nf][3]);
                lac[mf * 2]     += e0 + e1;
                lac[mf * 2 + 1] += e2 + e3;
                const int ccol = nbS + nf * 8 + tx * 2;
                *(float2*)&Ps[r * 132 + ccol] = make_float2(
                    __uint_as_float(f2tf(e0)), __uint_as_float(f2tf(e1)));
                *(float2*)&Ps[(r + 8) * 132 + ccol] = make_float2(
                    __uint_as_float(f2tf(e2)), __uint_as_float(f2tf(e3)));
            }
        }
        // visibility handled by the __syncthreads in the first PV chunk below

        // ---- O += P·Vt : 8 Vt chunks ----
#pragma unroll 1
        for (int jc = 0; jc < 8; jc++) {
            const int idx = t * 16 + 8 + jc;
            const int bf = idx % 3;
            CP_WAIT(1);
            __syncthreads();
            stage(idx + 2);
            const uint32_t vB = sB + bf * 20480 + vOff;
#pragma unroll
            for (int ks = 0; ks < 2; ks++) {
                uint32_t af[2][4], vf[8][4];
                ldsm4(af[0], pOff + jc * 64 + ks * 32);
                ldsm4(af[1], pOff + 16 * 528 + jc * 64 + ks * 32);
#pragma unroll
                for (int p = 0; p < 8; p++)
                    ldsm4(vf[p], vB + p * 16 * 80 + ks * 32);
#pragma unroll
                for (int mf = 0; mf < 2; mf++)
#pragma unroll
                    for (int p = 0; p < 8; p++) {
                        mma8(Oac[mf][2 * p],     af[mf], vf[p][0], vf[p][2]);
                        mma8(Oac[mf][2 * p + 1], af[mf], vf[p][1], vf[p][3]);
                    }
            }
        }
    }

    // ---- epilogue: reduce row sums, O/l, store ----
#pragma unroll
    for (int i = 0; i < 4; i++) {
        lac[i] += __shfl_xor_sync(0xffffffffu, lac[i], 1);
        lac[i] += __shfl_xor_sync(0xffffffffu, lac[i], 2);
    }
    __syncthreads();
    if (tx == 0) {
#pragma unroll
        for (int mf = 0; mf < 2; mf++) {
            lp[warpN * 128 + rb + mf * 16 + ty]     = lac[mf * 2];
            lp[warpN * 128 + rb + mf * 16 + ty + 8] = lac[mf * 2 + 1];
        }
    }
    __syncthreads();
#pragma unroll
    for (int mf = 0; mf < 2; mf++) {
        const int r0 = rb + mf * 16 + ty, r1 = r0 + 8;
        const float inv0 = 1.f / (lp[r0] + lp[128 + r0]);
        const float inv1 = 1.f / (lp[r1] + lp[128 + r1]);
        float* o0 = out + ((size_t)(bb * 1024 + q0 + r0)) * 2304 + cc * 768 + hh * 256 + nbO;
        float* o1 = out + ((size_t)(bb * 1024 + q0 + r1)) * 2304 + cc * 768 + hh * 256 + nbO;
#pragma unroll
        for (int nf = 0; nf < 16; nf++) {
            const int ccol = nf * 8 + tx * 2;
            *(float2*)&o0[ccol] = make_float2(Oac[mf][nf][0] * inv0, Oac[mf][nf][1] * inv0);
            *(float2*)&o1[ccol] = make_float2(Oac[mf][nf][2] * inv1, Oac[mf][nf][3] * inv1);
        }
    }
}

// ============================================================
extern "C" void kernel_launch(void* const* d_in, const int* in_sizes, int n_in,
                              void* d_out, int out_size)
{
    const float* x  = (const float*)d_in[0];
    const float* Wq = (const float*)d_in[1];
    const float* bq = (const float*)d_in[2];
    const float* Wk = (const float*)d_in[3];
    const float* bk = (const float*)d_in[4];
    const float* Wv = (const float*)d_in[5];
    const float* bv = (const float*)d_in[6];
    float* out = (float*)d_out;

    cudaFuncSetAttribute(qkv_mma,  cudaFuncAttributeMaxDynamicSharedMemorySize, QKV_SMEM);
    cudaFuncSetAttribute(attn_mma, cudaFuncAttributeMaxDynamicSharedMemorySize, ATT_SMEM);

    qkv_mma<<<dim3(16, 72, 3), 256, QKV_SMEM>>>(x, Wq, bq, Wk, bk, Wv, bv);
    attn_mma<<<dim3(8, 72), 256, ATT_SMEM>>>(out);
}

// round 12
// speedup vs baseline: 1.1581x; 1.1094x over previous
#include <cuda_runtime.h>
#include <cstdint>

#define SQ_ 0.09016844005556022f   // (1/16)*log2(e)

static __device__ float g_Q [18874368];   // [g][s][d]  scaled by SQ_, tf32-rounded
static __device__ float g_K [18874368];   // [g][s][d]  tf32-rounded
static __device__ float g_Vt[18874368];   // [g][e][s]  tf32-rounded

__device__ __forceinline__ uint32_t smem_u32(const void* p) {
    uint32_t a;
    asm("{ .reg .u64 t; cvta.to.shared.u64 t, %1; cvt.u32.u64 %0, t; }" : "=r"(a) : "l"(p));
    return a;
}
__device__ __forceinline__ void cpa16(uint32_t d, const void* s) {
    asm volatile("cp.async.cg.shared.global [%0], [%1], 16;\n" :: "r"(d), "l"(s));
}
#define CP_COMMIT  asm volatile("cp.async.commit_group;\n" ::: "memory")
#define CP_WAIT(n) asm volatile("cp.async.wait_group %0;\n" :: "n"(n) : "memory")

__device__ __forceinline__ uint32_t f2tf(float x) {
    uint32_t u; asm("cvt.rna.tf32.f32 %0, %1;" : "=r"(u) : "f"(x)); return u;
}
__device__ __forceinline__ float ex2f(float x) {
    float y; asm("ex2.approx.ftz.f32 %0, %1;" : "=f"(y) : "f"(x)); return y;
}
__device__ __forceinline__ void mma8(float* c, const uint32_t* a, const uint32_t b0, const uint32_t b1) {
    asm volatile("mma.sync.aligned.m16n8k8.row.col.f32.tf32.tf32.f32 "
                 "{%0,%1,%2,%3}, {%4,%5,%6,%7}, {%8,%9}, {%0,%1,%2,%3};\n"
                 : "+f"(c[0]), "+f"(c[1]), "+f"(c[2]), "+f"(c[3])
                 : "r"(a[0]), "r"(a[1]), "r"(a[2]), "r"(a[3]), "r"(b0), "r"(b1));
}
__device__ __forceinline__ void mma8u(uint32_t* c, const uint32_t* a, const uint32_t b0, const uint32_t b1) {
    mma8((float*)c, a, b0, b1);
}
__device__ __forceinline__ void ldsm4(uint32_t* r, uint32_t addr) {
    asm volatile("ldmatrix.sync.aligned.m8n8.x4.shared.b16 {%0,%1,%2,%3}, [%4];"
                 : "=r"(r[0]), "=r"(r[1]), "=r"(r[2]), "=r"(r[3]) : "r"(addr));
}

// ============================================================
// QKV (identical to the proven r7/r10 version): CTA 128x128, 256 thr,
// 3-stage cp.async ring.  Outputs tf32-rounded; Q pre-scaled; V transposed.
// ============================================================
#define QKV_SMEM 110592

__global__ void __launch_bounds__(256, 2)
qkv_mma(const float* __restrict__ x,
        const float* __restrict__ Wq, const float* __restrict__ bq,
        const float* __restrict__ Wk, const float* __restrict__ bk,
        const float* __restrict__ Wv, const float* __restrict__ bv)
{
    extern __shared__ float smf[];
    float* As = smf;            // 3 x 4608
    float* Bs = smf + 13824;    // 3 x 4608

    const int tile = blockIdx.x, g = blockIdx.y, z = blockIdx.z;
    const int tm = tile >> 1, tn = tile & 1;
    const int hh = g % 3;
    const int tid = threadIdx.x, wid = tid >> 5, lane = tid & 31;
    const int ty = lane >> 2, tx = lane & 3;
    const int warpM = wid >> 1, warpN = wid & 1;
    const int rb = warpM * 32, nb = warpN * 64;

    const float* W; const float* bias;
    if (z == 0)      { W = Wq; bias = bq; }
    else if (z == 1) { W = Wk; bias = bk; }
    else             { W = Wv; bias = bv; }
    W += hh * 65536;  bias += hh * 256;

    const float* X  = x + ((size_t)((g / 3) * 1024 + tm * 128)) * 768 + hh * 256;
    const float* Wp = W + tn * 128 * 256;
    const uint32_t sA = smem_u32(As), sB = smem_u32(Bs);

    auto stage = [&](int dc_) {
        if (dc_ >= 8) return;
        const int bf_ = dc_ % 3;
        uint32_t dA = sA + bf_ * 18432, dB = sB + bf_ * 18432;
#pragma unroll
        for (int it = 0; it < 4; it++) {
            int i = tid + it * 256, r = i >> 3, c4 = i & 7;
            cpa16(dA + r * 144 + c4 * 16, X  + (size_t)r * 768 + dc_ * 32 + c4 * 4);
            cpa16(dB + r * 144 + c4 * 16, Wp + r * 256 + dc_ * 32 + c4 * 4);
        }
        CP_COMMIT;
    };

    float acc[2][8][4];
#pragma unroll
    for (int mf = 0; mf < 2; mf++)
#pragma unroll
        for (int nf = 0; nf < 8; nf++)
#pragma unroll
            for (int k = 0; k < 4; k++) acc[mf][nf][k] = 0.f;

    stage(0); stage(1);
#pragma unroll 1
    for (int dc = 0; dc < 8; dc++) {
        const int bf = dc % 3;
        CP_WAIT(1);
        __syncthreads();
        stage(dc + 2);
        const float* Aq = As + bf * 4608;
        const float* Bk = Bs + bf * 4608;
#pragma unroll
        for (int ks = 0; ks < 4; ks++) {
            uint32_t af[2][4], bfr[8][2];
            const int kc = ks * 8 + tx;
#pragma unroll
            for (int mf = 0; mf < 2; mf++) {
                const float* ap = Aq + (rb + mf * 16 + ty) * 36 + kc;
                af[mf][0] = f2tf(ap[0]);
                af[mf][1] = f2tf(ap[8 * 36]);
                af[mf][2] = f2tf(ap[4]);
                af[mf][3] = f2tf(ap[8 * 36 + 4]);
            }
#pragma unroll
            for (int nf = 0; nf < 8; nf++) {
                const float* bp = Bk + (nb + nf * 8 + ty) * 36 + kc;
                bfr[nf][0] = f2tf(bp[0]);
                bfr[nf][1] = f2tf(bp[4]);
            }
#pragma unroll
            for (int mf = 0; mf < 2; mf++)
#pragma unroll
                for (int nf = 0; nf < 8; nf++)
                    mma8(acc[mf][nf], af[mf], bfr[nf][0], bfr[nf][1]);
        }
    }

    if (z < 2) {
        float* dst = (z == 0 ? g_Q : g_K) + (size_t)g * 262144;
        const float osc = (z == 0) ? SQ_ : 1.0f;
#pragma unroll
        for (int mf = 0; mf < 2; mf++) {
            const int r0 = tm * 128 + rb + mf * 16 + ty, r1 = r0 + 8;
#pragma unroll
            for (int nf = 0; nf < 8; nf++) {
                const int ccol = tn * 128 + nb + nf * 8 + tx * 2;
                const float b0 = __ldg(&bias[ccol]), b1 = __ldg(&bias[ccol + 1]);
                *(float2*)&dst[(size_t)r0 * 256 + ccol] = make_float2(
                    __uint_as_float(f2tf((acc[mf][nf][0] + b0) * osc)),
                    __uint_as_float(f2tf((acc[mf][nf][1] + b1) * osc)));
                *(float2*)&dst[(size_t)r1 * 256 + ccol] = make_float2(
                    __uint_as_float(f2tf((acc[mf][nf][2] + b0) * osc)),
                    __uint_as_float(f2tf((acc[mf][nf][3] + b1) * osc)));
            }
        }
    } else {
        float* dst = g_Vt + (size_t)g * 262144;
#pragma unroll
        for (int mf = 0; mf < 2; mf++) {
            const int r0 = tm * 128 + rb + mf * 16 + ty, r1 = r0 + 8;
#pragma unroll
            for (int nf = 0; nf < 8; nf++) {
                const int e0 = tn * 128 + nb + nf * 8 + tx * 2;
                const float b0 = __ldg(&bias[e0]), b1 = __ldg(&bias[e0 + 1]);
                dst[(size_t)e0 * 1024 + r0]       = __uint_as_float(f2tf(acc[mf][nf][0] + b0));
                dst[(size_t)(e0 + 1) * 1024 + r0] = __uint_as_float(f2tf(acc[mf][nf][1] + b1));
                dst[(size_t)e0 * 1024 + r1]       = __uint_as_float(f2tf(acc[mf][nf][2] + b0));
                dst[(size_t)(e0 + 1) * 1024 + r1] = __uint_as_float(f2tf(acc[mf][nf][3] + b1));
            }
        }
    }
}

// ============================================================
// Attention v2: per (qtile=128, g), 256 thr, 8 warps.
// Warp tile = 16 q-rows x 32-key block; P stays in registers via shuffle
// transpose (no P smem, no softmax barriers).  Q resident in smem (swizzled,
// 131072 B).  K/V stream in 32-key blocks (32768 B each, swizzled) through a
// 3-slot cp.async ring (sequence K0,V0,K1,V1,... slot=idx%3).
// smem total = 131072 + 3*32768 = 229376 B.
// ============================================================
#define ATT_SMEM 229376

__global__ void __launch_bounds__(256, 1)
attn_mma(float* __restrict__ out)
{
    extern __shared__ float smf[];
    const int qt = blockIdx.x, g = blockIdx.y;
    const int bb = g / 9, cc = (g / 3) % 3, hh = g % 3;
    const int q0 = qt * 128;
    const int tid = threadIdx.x, wid = tid >> 5, lane = tid & 31;
    const int ty = lane >> 2, tx = lane & 3;
    const int rb = wid * 16;                      // 16 q-rows per warp
    const size_t gbase = (size_t)g * 262144;
    const float* Qg = g_Q + gbase + (size_t)q0 * 256;
    const float* Kg = g_K + gbase;
    const float* Vg = g_Vt + gbase;
    const uint32_t sQ = smem_u32(smf);
    const uint32_t sR = sQ + 131072;

    const int lrow = lane & 15;
    const int kh   = lane >> 4;
    const uint32_t xr = (uint32_t)(lane & 7) << 4;         // XOR swizzle term
    const uint32_t qA = sQ + (uint32_t)(rb + lrow) * 1024; // Q row base

    // ---- stage Q once (swizzled): 128 rows x 64 float4 ----
#pragma unroll
    for (int it = 0; it < 32; it++) {
        int i = tid + it * 256;
        int r = i >> 6, c4 = i & 63;
        cpa16(sQ + r * 1024 + ((uint32_t)(c4 ^ (r & 7)) << 4),
              Qg + (size_t)r * 256 + c4 * 4);
    }
    CP_COMMIT;

    // loads idx 0..63: even -> K block idx/2, odd -> V block idx/2; slot idx%3
    auto stage = [&](int idx) {
        if (idx >= 64) return;
        const int kb_ = idx >> 1, slot = idx % 3;
        const uint32_t dB = sR + slot * 32768;
        if ((idx & 1) == 0) {       // K: 32 keys x 256 d
            const float* Kc = Kg + (size_t)(kb_ * 32) * 256;
#pragma unroll
            for (int it = 0; it < 8; it++) {
                int i = tid + it * 256;
                int r = i >> 6, c4 = i & 63;
                cpa16(dB + r * 1024 + ((uint32_t)(c4 ^ (r & 7)) << 4),
                      Kc + (size_t)r * 256 + c4 * 4);
            }
        } else {                    // V: 256 e x 32 s
            const float* Vc = Vg + kb_ * 32;
#pragma unroll
            for (int it = 0; it < 8; it++) {
                int i = tid + it * 256;
                int e = i >> 3, c4 = i & 7;
                cpa16(dB + e * 128 + ((uint32_t)(c4 ^ (e & 7)) << 4),
                      Vc + (size_t)e * 1024 + c4 * 4);
            }
        }
        CP_COMMIT;
    };

    float Oac[32][4];
#pragma unroll
    for (int j = 0; j < 32; j++)
#pragma unroll
        for (int k = 0; k < 4; k++) Oac[j][k] = 0.f;
    float lac0 = 0.f, lac1 = 0.f;
    uint32_t pa[4][4];

    stage(0); stage(1);

#pragma unroll 1
    for (int kb = 0; kb < 32; kb++) {
        // ---- S = Q . K^T for this 32-key block ----
        CP_WAIT(1);
        __syncthreads();
        stage(2 * kb + 2);
        {
            const uint32_t kA = sR + ((2 * kb) % 3) * 32768 + (uint32_t)lrow * 1024;
            float Sac[4][4];
#pragma unroll
            for (int nf = 0; nf < 4; nf++)
#pragma unroll
                for (int k = 0; k < 4; k++) Sac[nf][k] = 0.f;
#pragma unroll
            for (int ks = 0; ks < 32; ks++) {
                uint32_t af[4], b0[4], b1[4];
                const uint32_t so = ((uint32_t)(ks * 2 + kh) << 4) ^ xr;
                ldsm4(af, qA + so);
                ldsm4(b0, kA + so);
                ldsm4(b1, kA + 16384 + so);
                mma8(Sac[0], af, b0[0], b0[2]);
                mma8(Sac[1], af, b0[1], b0[3]);
                mma8(Sac[2], af, b1[0], b1[2]);
                mma8(Sac[3], af, b1[1], b1[3]);
            }

            // ---- softmax (ref max 0) + register transpose to PV A-frags ----
            const int srcA = (lane & 28) | (tx >> 1);
            const int srcB = srcA + 2;
            const bool odd = (tx & 1);
#pragma unroll
            for (int nf = 0; nf < 4; nf++) {
                float e0 = ex2f(Sac[nf][0]);
                float e1 = ex2f(Sac[nf][1]);
                float e2 = ex2f(Sac[nf][2]);
                float e3 = ex2f(Sac[nf][3]);
                lac0 += e0 + e1;
                lac1 += e2 + e3;
                uint32_t s0 = f2tf(e0), s1 = f2tf(e1), s2 = f2tf(e2), s3 = f2tf(e3);
                uint32_t u0 = __shfl_sync(0xffffffffu, s0, srcA);
                uint32_t u1 = __shfl_sync(0xffffffffu, s1, srcA);
                uint32_t u2 = __shfl_sync(0xffffffffu, s2, srcA);
                uint32_t u3 = __shfl_sync(0xffffffffu, s3, srcA);
                uint32_t v0 = __shfl_sync(0xffffffffu, s0, srcB);
                uint32_t v1 = __shfl_sync(0xffffffffu, s1, srcB);
                uint32_t v2 = __shfl_sync(0xffffffffu, s2, srcB);
                uint32_t v3 = __shfl_sync(0xffffffffu, s3, srcB);
                pa[nf][0] = odd ? u1 : u0;   // P[ty][nf*8+tx]
                pa[nf][1] = odd ? u3 : u2;   // P[ty+8][nf*8+tx]
                pa[nf][2] = odd ? v1 : v0;   // P[ty][nf*8+tx+4]
                pa[nf][3] = odd ? v3 : v2;   // P[ty+8][nf*8+tx+4]
            }
        }

        // ---- O += P . Vt for this block ----
        CP_WAIT(1);
        __syncthreads();
        stage(2 * kb + 3);
        {
            const uint32_t vA = sR + ((2 * kb + 1) % 3) * 32768 + (uint32_t)lrow * 128;
#pragma unroll
            for (int ks = 0; ks < 4; ks++) {
                const uint32_t so = ((uint32_t)(ks * 2 + kh) << 4) ^ xr;
#pragma unroll
                for (int p = 0; p < 16; p++) {
                    uint32_t vf[4];
                    ldsm4(vf, vA + p * 2048 + so);
                    mma8(Oac[2 * p],     pa[ks], vf[0], vf[2]);
                    mma8(Oac[2 * p + 1], pa[ks], vf[1], vf[3]);
                }
            }
        }
    }

    // ---- epilogue: warp-local row sums, O/l, store ----
    lac0 += __shfl_xor_sync(0xffffffffu, lac0, 1);
    lac0 += __shfl_xor_sync(0xffffffffu, lac0, 2);
    lac1 += __shfl_xor_sync(0xffffffffu, lac1, 1);
    lac1 += __shfl_xor_sync(0xffffffffu, lac1, 2);
    const float inv0 = 1.f / lac0;
    const float inv1 = 1.f / lac1;
    const int r0 = q0 + rb + ty;
    float* o0 = out + ((size_t)(bb * 1024 + r0)) * 2304 + cc * 768 + hh * 256;
    float* o1 = o0 + (size_t)8 * 2304;
#pragma unroll
    for (int j = 0; j < 32; j++) {
        const int ccol = j * 8 + tx * 2;
        *(float2*)&o0[ccol] = make_float2(Oac[j][0] * inv0, Oac[j][1] * inv0);
        *(float2*)&o1[ccol] = make_float2(Oac[j][2] * inv1, Oac[j][3] * inv1);
    }
}

// ============================================================
extern "C" void kernel_launch(void* const* d_in, const int* in_sizes, int n_in,
                              void* d_out, int out_size)
{
    const float* x  = (const float*)d_in[0];
    const float* Wq = (const float*)d_in[1];
    const float* bq = (const float*)d_in[2];
    const float* Wk = (const float*)d_in[3];
    const float* bk = (const float*)d_in[4];
    const float* Wv = (const float*)d_in[5];
    const float* bv = (const float*)d_in[6];
    float* out = (float*)d_out;

    cudaFuncSetAttribute(qkv_mma,  cudaFuncAttributeMaxDynamicSharedMemorySize, QKV_SMEM);
    cudaFuncSetAttribute(attn_mma, cudaFuncAttributeMaxDynamicSharedMemorySize, ATT_SMEM);

    qkv_mma<<<dim3(16, 72, 3), 256, QKV_SMEM>>>(x, Wq, bq, Wk, bk, Wv, bv);
    attn_mma<<<dim3(8, 72), 256, ATT_SMEM>>>(out);
}